// round 3
// baseline (speedup 1.0000x reference)
#include <cuda_runtime.h>
#include <cuda_bf16.h>
#include <cstdint>

// Problem constants
#define B_DIM 4096
#define F_DIM 512
#define T_DIM 2048
#define N_TOTAL 8192            // T*D
#define TAU_F 0.2018004745467103f

// GEMM tiling: CTA 128(M) x 256(N), 8 warps in 2(M) x 4(N), warp tile 64x64
#define MT 128
#define NT 256
#define KC 64                   // K elements per smem stage
#define NCHUNK 8                // 512/64
#define NSTAGE 3
#define THREADS 256
#define A_STAGE_BYTES 16384     // 128 x 64 bf16
#define B_STAGE_BYTES 32768     // 256 x 64 bf16
#define STAGE_BYTES (A_STAGE_BYTES + B_STAGE_BYTES)
#define SM_TOTAL (NSTAGE * STAGE_BYTES)      // 147456
#define EPI_STRIDE 68           // floats; float4-aligned, bank-rotating

// Scratch (device globals: allocation-free rule)
__device__ __nv_bfloat16 g_W[N_TOTAL * F_DIM];   // softmax(feature_logits), K-major bf16
__device__ __nv_bfloat16 g_X[B_DIM * F_DIM];     // x in bf16

// ---------------- helpers ----------------
__device__ __forceinline__ uint32_t smem_u32(const void* p) {
    uint32_t a;
    asm("{ .reg .u64 t; cvta.to.shared.u64 t, %1; cvt.u32.u64 %0, t; }" : "=r"(a) : "l"(p));
    return a;
}
__device__ __forceinline__ uint32_t swz128(uint32_t off) {   // SW128: bits[6:4] ^= bits[9:7]
    return off ^ ((off >> 3) & 0x70);
}
__device__ __forceinline__ void cp_async16(uint32_t dst, const void* src) {
    asm volatile("cp.async.cg.shared.global [%0], [%1], 16;\n" :: "r"(dst), "l"(src) : "memory");
}
__device__ __forceinline__ void cp_commit() { asm volatile("cp.async.commit_group;\n" ::: "memory"); }
template <int N> __device__ __forceinline__ void cp_wait() {
    asm volatile("cp.async.wait_group %0;\n" :: "n"(N) : "memory");
}
__device__ __forceinline__ void ldsm_x4(uint32_t* r, uint32_t addr) {
    asm volatile("ldmatrix.sync.aligned.m8n8.x4.shared.b16 {%0,%1,%2,%3}, [%4];"
                 : "=r"(r[0]), "=r"(r[1]), "=r"(r[2]), "=r"(r[3]) : "r"(addr));
}
__device__ __forceinline__ void mma16816(float* c, const uint32_t* a, uint32_t b0, uint32_t b1) {
    asm volatile("mma.sync.aligned.m16n8k16.row.col.f32.bf16.bf16.f32 "
                 "{%0,%1,%2,%3}, {%4,%5,%6,%7}, {%8,%9}, {%0,%1,%2,%3};"
                 : "+f"(c[0]), "+f"(c[1]), "+f"(c[2]), "+f"(c[3])
                 : "r"(a[0]), "r"(a[1]), "r"(a[2]), "r"(a[3]), "r"(b0), "r"(b1));
}

// ---------------- prep kernels ----------------
__global__ void k_convert_x(const float* __restrict__ x) {
    int i = (blockIdx.x * blockDim.x + threadIdx.x) * 4;
    if (i < B_DIM * F_DIM) {
        float4 v = *reinterpret_cast<const float4*>(x + i);
        __nv_bfloat162 lo = __floats2bfloat162_rn(v.x, v.y);
        __nv_bfloat162 hi = __floats2bfloat162_rn(v.z, v.w);
        *reinterpret_cast<uint32_t*>(g_X + i)     = *reinterpret_cast<uint32_t*>(&lo);
        *reinterpret_cast<uint32_t*>(g_X + i + 2) = *reinterpret_cast<uint32_t*>(&hi);
    }
}

__global__ void k_softmax(const float* __restrict__ logits) {
    int warp = (blockIdx.x * blockDim.x + threadIdx.x) >> 5;   // one warp per (t,d) row
    int lane = threadIdx.x & 31;
    if (warp >= N_TOTAL) return;
    const float* row = logits + (size_t)warp * F_DIM;
    float v[16], vmax = -1e30f;
#pragma unroll
    for (int i = 0; i < 16; i++) { v[i] = row[lane + i * 32]; vmax = fmaxf(vmax, v[i]); }
#pragma unroll
    for (int o = 16; o > 0; o >>= 1) vmax = fmaxf(vmax, __shfl_xor_sync(0xFFFFFFFFu, vmax, o));
    float s = 0.f;
#pragma unroll
    for (int i = 0; i < 16; i++) { v[i] = __expf(v[i] - vmax); s += v[i]; }
#pragma unroll
    for (int o = 16; o > 0; o >>= 1) s += __shfl_xor_sync(0xFFFFFFFFu, s, o);
    float inv = __fdividef(1.0f, s);
    __nv_bfloat16* out = g_W + (size_t)warp * F_DIM;
#pragma unroll
    for (int i = 0; i < 16; i++) out[lane + i * 32] = __float2bfloat16(v[i] * inv);
}

// ---------------- fused GEMM + tree epilogue ----------------
__device__ __forceinline__ void load_stage(uint32_t sbase, int tid, int chunk,
                                           const __nv_bfloat16* Abase, const __nv_bfloat16* Bbase) {
    uint32_t dst = sbase + (chunk % NSTAGE) * STAGE_BYTES;
    const char* srcA = reinterpret_cast<const char*>(Abase) + chunk * (KC * 2);
    const char* srcB = reinterpret_cast<const char*>(Bbase) + chunk * (KC * 2);
#pragma unroll
    for (int i = 0; i < 4; i++) {            // A: 128 rows x 8 x 16B
        int idx = tid + i * THREADS;
        int row = idx >> 3, seg = idx & 7;
        cp_async16(dst + swz128(row * 128 + seg * 16), srcA + row * 1024 + seg * 16);
    }
#pragma unroll
    for (int i = 0; i < 8; i++) {            // B: 256 rows x 8 x 16B
        int idx = tid + i * THREADS;
        int row = idx >> 3, seg = idx & 7;
        cp_async16(dst + A_STAGE_BYTES + swz128(row * 128 + seg * 16), srcB + row * 1024 + seg * 16);
    }
}

__global__ void __launch_bounds__(THREADS, 1)
k_main(const float* __restrict__ thr, const float* __restrict__ leaf, float* __restrict__ out) {
    extern __shared__ char smem[];
    uint32_t sbase = smem_u32(smem);
    int tid = threadIdx.x;
    int wid = tid >> 5, lane = tid & 31;
    int wm = wid & 1, wn = wid >> 1;         // 2x4 warp grid; warp tile 64(M) x 64(N)
    int m0 = blockIdx.x * MT;
    int n0 = blockIdx.y * NT;

    const __nv_bfloat16* Abase = g_X + (size_t)m0 * F_DIM;
    const __nv_bfloat16* Bbase = g_W + (size_t)n0 * F_DIM;

    load_stage(sbase, tid, 0, Abase, Bbase); cp_commit();
    load_stage(sbase, tid, 1, Abase, Bbase); cp_commit();
    load_stage(sbase, tid, 2, Abase, Bbase); cp_commit();

    float acc[4][8][4];                      // [m16 frag][n8 tile][quad]
#pragma unroll
    for (int i = 0; i < 4; i++)
#pragma unroll
        for (int j = 0; j < 8; j++)
#pragma unroll
            for (int q = 0; q < 4; q++) acc[i][j][q] = 0.f;

    int arow0 = wm * 64 + (lane & 15);       // A rows; mf in {0..3} adds 16 each
    int brow0 = wn * 64 + (lane & 15);       // B rows; tp in {0..3} adds 16 each
    int khalf = (lane >> 4) * 16;            // 16B half select within k16

#pragma unroll 1
    for (int c = 0; c < NCHUNK; c++) {
        cp_wait<NSTAGE - 1>();
        __syncthreads();
        uint32_t aB = sbase + (c % NSTAGE) * STAGE_BYTES;
        uint32_t bB = aB + A_STAGE_BYTES;
#pragma unroll
        for (int s = 0; s < 4; s++) {        // 4 x k16 steps per 64-K stage
            int koff = s * 32 + khalf;
            uint32_t a[4][4];
#pragma unroll
            for (int mf = 0; mf < 4; mf++)
                ldsm_x4(a[mf], aB + swz128((arow0 + mf * 16) * 128 + koff));
#pragma unroll
            for (int tp = 0; tp < 4; tp++) { // 2 n8-tiles per B ldmatrix.x4
                uint32_t b[4];
                ldsm_x4(b, bB + swz128((brow0 + tp * 16) * 128 + koff));
#pragma unroll
                for (int mf = 0; mf < 4; mf++) {
                    mma16816(acc[mf][tp * 2],     a[mf], b[0], b[2]);
                    mma16816(acc[mf][tp * 2 + 1], a[mf], b[1], b[3]);
                }
            }
        }
        __syncthreads();
        if (c + NSTAGE < NCHUNK) load_stage(sbase, tid, c + NSTAGE, Abase, Bbase);
        cp_commit();                          // uniform group accounting
    }

    // ---- Epilogue: stage acc -> smem (warp-private), fold trees, write out ----
    __syncthreads();                          // all warps done with stage buffers
    float* epi = reinterpret_cast<float*>(smem) + wid * 64 * EPI_STRIDE;
    int grp = lane >> 2, qc = (lane & 3) * 2;
#pragma unroll
    for (int mf = 0; mf < 4; mf++)
#pragma unroll
        for (int nt = 0; nt < 8; nt++) {
            int row = mf * 16 + grp;
            int col = nt * 8 + qc;
            epi[row * EPI_STRIDE + col]           = acc[mf][nt][0];
            epi[row * EPI_STRIDE + col + 1]       = acc[mf][nt][1];
            epi[(row + 8) * EPI_STRIDE + col]     = acc[mf][nt][2];
            epi[(row + 8) * EPI_STRIDE + col + 1] = acc[mf][nt][3];
        }
    __syncwarp();

    // Each lane owns one tree (lane&15); half-warps interleave the 64 rows.
    int tl = lane & 15;
    int tglob = (n0 + wn * 64) / 4 + tl;
    const float inv_tau = 1.0f / TAU_F;
    float th[4];
#pragma unroll
    for (int d = 0; d < 4; d++) th[d] = thr[tglob * 4 + d];
    float L[16];
    const float4* Lv = reinterpret_cast<const float4*>(leaf + (size_t)tglob * 16);
#pragma unroll
    for (int i = 0; i < 4; i++) {
        float4 v = Lv[i];
        L[i * 4] = v.x; L[i * 4 + 1] = v.y; L[i * 4 + 2] = v.z; L[i * 4 + 3] = v.w;
    }

#pragma unroll 4
    for (int i = 0; i < 32; i++) {
        int row = (lane >> 4) + 2 * i;
        float4 xs = *reinterpret_cast<const float4*>(epi + row * EPI_STRIDE + 4 * tl);
        float p[4];
        float zv[4] = {xs.x, xs.y, xs.z, xs.w};
#pragma unroll
        for (int d = 0; d < 4; d++) {
            float z = (zv[d] - th[d]) * inv_tau;
            float e = __expf(-z);
            p[d] = __fdividef(1.0f, 1.0f + e);
        }
        float g[8];
#pragma unroll
        for (int k = 0; k < 8; k++) g[k] = fmaf(p[3], L[8 + k] - L[k], L[k]);
        float h[4];
#pragma unroll
        for (int k = 0; k < 4; k++) h[k] = fmaf(p[2], g[4 + k] - g[k], g[k]);
        float e2[2];
#pragma unroll
        for (int k = 0; k < 2; k++) e2[k] = fmaf(p[1], h[2 + k] - h[k], h[k]);
        float val = fmaf(p[0], e2[1] - e2[0], e2[0]);
        out[(size_t)(m0 + wm * 64 + row) * T_DIM + tglob] = val;
    }
}

// ---------------- launch ----------------
extern "C" void kernel_launch(void* const* d_in, const int* in_sizes, int n_in,
                              void* d_out, int out_size) {
    const float* x      = (const float*)d_in[0];
    const float* logits = (const float*)d_in[1];
    const float* thr    = (const float*)d_in[2];
    const float* leaf   = (const float*)d_in[3];
    float* out = (float*)d_out;

    k_convert_x<<<(B_DIM * F_DIM / 4 + 255) / 256, 256>>>(x);
    k_softmax<<<(N_TOTAL * 32) / 256, 256>>>(logits);

    cudaFuncSetAttribute(k_main, cudaFuncAttributeMaxDynamicSharedMemorySize, SM_TOTAL);
    dim3 grid(B_DIM / MT, N_TOTAL / NT);
    k_main<<<grid, THREADS, SM_TOTAL>>>(thr, leaf, out);
}

// round 4
// speedup vs baseline: 1.1571x; 1.1571x over previous
#include <cuda_runtime.h>
#include <cuda_bf16.h>
#include <cstdint>

// Problem constants
#define B_DIM 4096
#define F_DIM 512
#define T_DIM 2048
#define N_TOTAL 8192            // T*D
#define TAU_F 0.2018004745467103f

// GEMM tiling: CTA 128x128, 8 warps in 4(M) x 2(N), warp tile 32x64
#define MT 128
#define NT 128
#define KC 64                   // K elements per smem stage
#define NCHUNK 8                // 512/64
#define NSTAGE 3
#define THREADS 256
#define STAGE_BYTES 32768       // (128+128)*64*2
#define SM_TOTAL (NSTAGE * STAGE_BYTES)      // 98304 -> 2 CTAs/SM
#define EPI_STRIDE 68           // floats; float4-aligned, bank-rotating

// Scratch (device globals: allocation-free rule)
__device__ __nv_bfloat16 g_W[N_TOTAL * F_DIM];   // softmax(feature_logits), K-major bf16
__device__ __nv_bfloat16 g_X[B_DIM * F_DIM];     // x in bf16

// ---------------- helpers ----------------
__device__ __forceinline__ uint32_t smem_u32(const void* p) {
    uint32_t a;
    asm("{ .reg .u64 t; cvta.to.shared.u64 t, %1; cvt.u32.u64 %0, t; }" : "=r"(a) : "l"(p));
    return a;
}
__device__ __forceinline__ uint32_t swz128(uint32_t off) {   // SW128: bits[6:4] ^= bits[9:7]
    return off ^ ((off >> 3) & 0x70);
}
__device__ __forceinline__ void cp_async16(uint32_t dst, const void* src) {
    asm volatile("cp.async.cg.shared.global [%0], [%1], 16;\n" :: "r"(dst), "l"(src) : "memory");
}
__device__ __forceinline__ void cp_commit() { asm volatile("cp.async.commit_group;\n" ::: "memory"); }
template <int N> __device__ __forceinline__ void cp_wait() {
    asm volatile("cp.async.wait_group %0;\n" :: "n"(N) : "memory");
}
__device__ __forceinline__ void ldsm_x4(uint32_t* r, uint32_t addr) {
    asm volatile("ldmatrix.sync.aligned.m8n8.x4.shared.b16 {%0,%1,%2,%3}, [%4];"
                 : "=r"(r[0]), "=r"(r[1]), "=r"(r[2]), "=r"(r[3]) : "r"(addr));
}
__device__ __forceinline__ void mma16816(float* c, const uint32_t* a, uint32_t b0, uint32_t b1) {
    asm volatile("mma.sync.aligned.m16n8k16.row.col.f32.bf16.bf16.f32 "
                 "{%0,%1,%2,%3}, {%4,%5,%6,%7}, {%8,%9}, {%0,%1,%2,%3};"
                 : "+f"(c[0]), "+f"(c[1]), "+f"(c[2]), "+f"(c[3])
                 : "r"(a[0]), "r"(a[1]), "r"(a[2]), "r"(a[3]), "r"(b0), "r"(b1));
}

// ---------------- fused prep kernel ----------------
// blocks [0,1024): convert x -> bf16 (8 elems/thread)
// blocks [1024,2048): softmax rows (8 warps/block, one row/warp)
__global__ void __launch_bounds__(256) k_prep(const float* __restrict__ x,
                                              const float* __restrict__ logits) {
    if (blockIdx.x < 1024) {
        int i = (blockIdx.x * 256 + threadIdx.x) * 8;
#pragma unroll
        for (int half = 0; half < 2; half++) {
            float4 v = *reinterpret_cast<const float4*>(x + i + half * 4);
            __nv_bfloat162 lo = __floats2bfloat162_rn(v.x, v.y);
            __nv_bfloat162 hi = __floats2bfloat162_rn(v.z, v.w);
            *reinterpret_cast<uint32_t*>(g_X + i + half * 4)     = *reinterpret_cast<uint32_t*>(&lo);
            *reinterpret_cast<uint32_t*>(g_X + i + half * 4 + 2) = *reinterpret_cast<uint32_t*>(&hi);
        }
    } else {
        int warp = (blockIdx.x - 1024) * 8 + (threadIdx.x >> 5);   // one warp per (t,d) row
        int lane = threadIdx.x & 31;
        const float* row = logits + (size_t)warp * F_DIM;
        float v[16], vmax = -1e30f;
#pragma unroll
        for (int i = 0; i < 16; i++) { v[i] = row[lane + i * 32]; vmax = fmaxf(vmax, v[i]); }
#pragma unroll
        for (int o = 16; o > 0; o >>= 1) vmax = fmaxf(vmax, __shfl_xor_sync(0xFFFFFFFFu, vmax, o));
        float s = 0.f;
#pragma unroll
        for (int i = 0; i < 16; i++) { v[i] = __expf(v[i] - vmax); s += v[i]; }
#pragma unroll
        for (int o = 16; o > 0; o >>= 1) s += __shfl_xor_sync(0xFFFFFFFFu, s, o);
        float inv = __fdividef(1.0f, s);
        __nv_bfloat16* out = g_W + (size_t)warp * F_DIM;
#pragma unroll
        for (int i = 0; i < 16; i++) out[lane + i * 32] = __float2bfloat16(v[i] * inv);
    }
}

// ---------------- fused GEMM + tree epilogue ----------------
__device__ __forceinline__ void load_stage(uint32_t sbase, int tid, int chunk,
                                           const __nv_bfloat16* Abase, const __nv_bfloat16* Bbase) {
    uint32_t dst = sbase + (chunk % NSTAGE) * STAGE_BYTES;
    const char* srcA = reinterpret_cast<const char*>(Abase) + chunk * (KC * 2);
    const char* srcB = reinterpret_cast<const char*>(Bbase) + chunk * (KC * 2);
#pragma unroll
    for (int i = 0; i < 4; i++) {            // A: 128 rows x 8 x 16B
        int idx = tid + i * THREADS;
        int row = idx >> 3, seg = idx & 7;
        cp_async16(dst + swz128(row * 128 + seg * 16), srcA + row * 1024 + seg * 16);
    }
#pragma unroll
    for (int i = 0; i < 4; i++) {            // B: 128 rows x 8 x 16B
        int idx = tid + i * THREADS;
        int row = idx >> 3, seg = idx & 7;
        cp_async16(dst + 16384 + swz128(row * 128 + seg * 16), srcB + row * 1024 + seg * 16);
    }
    cp_commit();
}

__global__ void __launch_bounds__(THREADS, 2)
k_main(const float* __restrict__ thr, const float* __restrict__ leaf, float* __restrict__ out) {
    extern __shared__ char smem[];
    uint32_t sbase = smem_u32(smem);
    int tid = threadIdx.x;
    int wid = tid >> 5, lane = tid & 31;
    int wm = wid & 3, wn = wid >> 2;         // 4x2 warp grid; warp tile 32(M) x 64(N)
    int m0 = blockIdx.x * MT;
    int n0 = blockIdx.y * NT;

    const __nv_bfloat16* Abase = g_X + (size_t)m0 * F_DIM;
    const __nv_bfloat16* Bbase = g_W + (size_t)n0 * F_DIM;

    load_stage(sbase, tid, 0, Abase, Bbase);
    load_stage(sbase, tid, 1, Abase, Bbase);

    float acc[2][8][4];
#pragma unroll
    for (int i = 0; i < 2; i++)
#pragma unroll
        for (int j = 0; j < 8; j++)
#pragma unroll
            for (int q = 0; q < 4; q++) acc[i][j][q] = 0.f;

    int arow0 = wm * 32 + (lane & 15);       // A rows for mf=0 (mf=1 adds 16)
    int brow0 = wn * 64 + (lane & 15);       // B rows for tp=0 (tp adds 16 each)
    int khalf = (lane >> 4) * 16;            // 16B half select within k16

#pragma unroll 1
    for (int c = 0; c < NCHUNK; c++) {
        if (c == NCHUNK - 1) cp_wait<0>(); else cp_wait<1>();
        __syncthreads();                     // single barrier: stage c ready AND
                                             // all warps done with stage c-1 (its buffer
                                             // is the one load_stage(c+2) overwrites)
        if (c + 2 < NCHUNK) load_stage(sbase, tid, c + 2, Abase, Bbase);

        uint32_t aB = sbase + (c % NSTAGE) * STAGE_BYTES;
        uint32_t bB = aB + 16384;
#pragma unroll
        for (int s = 0; s < 4; s++) {        // 4 x k16 steps in this 64-K stage
            int koff = s * 32 + khalf;
            uint32_t a[2][4];
#pragma unroll
            for (int mf = 0; mf < 2; mf++)
                ldsm_x4(a[mf], aB + swz128((arow0 + mf * 16) * 128 + koff));
#pragma unroll
            for (int tp = 0; tp < 4; tp++) { // 2 n8-tiles per B ldmatrix.x4
                uint32_t b[4];
                ldsm_x4(b, bB + swz128((brow0 + tp * 16) * 128 + koff));
                mma16816(acc[0][tp * 2],     a[0], b[0], b[2]);
                mma16816(acc[0][tp * 2 + 1], a[0], b[1], b[3]);
                mma16816(acc[1][tp * 2],     a[1], b[0], b[2]);
                mma16816(acc[1][tp * 2 + 1], a[1], b[1], b[3]);
            }
        }
    }

    // ---- Epilogue: stage acc -> smem (warp-private), fold trees, write out ----
    __syncthreads();                          // all warps done reading stage buffers
    float* epi = reinterpret_cast<float*>(smem) + wid * 32 * EPI_STRIDE;
    int grp = lane >> 2, qc = (lane & 3) * 2;
#pragma unroll
    for (int mf = 0; mf < 2; mf++)
#pragma unroll
        for (int nt = 0; nt < 8; nt++) {
            int row = mf * 16 + grp;
            int col = nt * 8 + qc;
            epi[row * EPI_STRIDE + col]           = acc[mf][nt][0];
            epi[row * EPI_STRIDE + col + 1]       = acc[mf][nt][1];
            epi[(row + 8) * EPI_STRIDE + col]     = acc[mf][nt][2];
            epi[(row + 8) * EPI_STRIDE + col + 1] = acc[mf][nt][3];
        }
    __syncwarp();

    // Each lane owns one tree (lane&15) across 32 rows split by half-warp.
    int tl = lane & 15;
    int tglob = (n0 + wn * 64) / 4 + tl;
    const float inv_tau = 1.0f / TAU_F;
    float th[4];
#pragma unroll
    for (int d = 0; d < 4; d++) th[d] = thr[tglob * 4 + d];
    float L[16];
    const float4* Lv = reinterpret_cast<const float4*>(leaf + (size_t)tglob * 16);
#pragma unroll
    for (int i = 0; i < 4; i++) {
        float4 v = Lv[i];
        L[i * 4] = v.x; L[i * 4 + 1] = v.y; L[i * 4 + 2] = v.z; L[i * 4 + 3] = v.w;
    }

#pragma unroll
    for (int i = 0; i < 16; i++) {
        int row = (lane >> 4) + 2 * i;
        float4 xs = *reinterpret_cast<const float4*>(epi + row * EPI_STRIDE + 4 * tl);
        float p[4];
        float zv[4] = {xs.x, xs.y, xs.z, xs.w};
#pragma unroll
        for (int d = 0; d < 4; d++) {
            float z = (zv[d] - th[d]) * inv_tau;
            float e = __expf(-z);
            p[d] = __fdividef(1.0f, 1.0f + e);
        }
        float g[8];
#pragma unroll
        for (int k = 0; k < 8; k++) g[k] = fmaf(p[3], L[8 + k] - L[k], L[k]);
        float h[4];
#pragma unroll
        for (int k = 0; k < 4; k++) h[k] = fmaf(p[2], g[4 + k] - g[k], g[k]);
        float e2[2];
#pragma unroll
        for (int k = 0; k < 2; k++) e2[k] = fmaf(p[1], h[2 + k] - h[k], h[k]);
        float val = fmaf(p[0], e2[1] - e2[0], e2[0]);
        out[(size_t)(m0 + wm * 32 + row) * T_DIM + tglob] = val;
    }
}

// ---------------- launch ----------------
extern "C" void kernel_launch(void* const* d_in, const int* in_sizes, int n_in,
                              void* d_out, int out_size) {
    const float* x      = (const float*)d_in[0];
    const float* logits = (const float*)d_in[1];
    const float* thr    = (const float*)d_in[2];
    const float* leaf   = (const float*)d_in[3];
    float* out = (float*)d_out;

    k_prep<<<2048, 256>>>(x, logits);

    cudaFuncSetAttribute(k_main, cudaFuncAttributeMaxDynamicSharedMemorySize, SM_TOTAL);
    dim3 grid(B_DIM / MT, N_TOTAL / NT);
    k_main<<<grid, THREADS, SM_TOTAL>>>(thr, leaf, out);
}